// round 9
// baseline (speedup 1.0000x reference)
#include <cuda_runtime.h>
#include <cuda_bf16.h>
#include <math.h>
#include <stdint.h>

#define Bsz 256
#define Tn  256
#define In  128
#define Hn  512
#define NCTA 128

// ---------------- device scratch ----------------
__device__ float g_xs[(size_t)Tn * Bsz * Hn];
__device__ __nv_bfloat16 g_hhi[2][Bsz * Hn];   // ping-pong hidden hi (plain row-major)
__device__ __nv_bfloat16 g_hlo[2][Bsz * Hn];   // ping-pong hidden lo
__device__ float g_hT[Bsz * Hn];
__device__ unsigned int g_barA[8 * 32];   // per m-group counter, kc0 producers (cols 0..255)
__device__ unsigned int g_barB[8 * 32];   // kc1 producers (cols 256..511)

// ---------------- helpers ----------------
__device__ __forceinline__ uint32_t smem_u32(const void* p) {
    uint32_t a;
    asm("{ .reg .u64 t; cvta.to.shared.u64 t, %1; cvt.u32.u64 %0, t; }" : "=r"(a) : "l"(p));
    return a;
}
__device__ __forceinline__ void ldsm4(uint32_t r[4], uint32_t addr) {
    asm volatile("ldmatrix.sync.aligned.m8n8.x4.shared.b16 {%0,%1,%2,%3}, [%4];"
                 : "=r"(r[0]), "=r"(r[1]), "=r"(r[2]), "=r"(r[3]) : "r"(addr));
}
__device__ __forceinline__ void mma_bf16(float c[4], const uint32_t a[4], uint32_t b0, uint32_t b1) {
    asm volatile("mma.sync.aligned.m16n8k16.row.col.f32.bf16.bf16.f32 "
                 "{%0,%1,%2,%3},{%4,%5,%6,%7},{%8,%9},{%0,%1,%2,%3};"
                 : "+f"(c[0]), "+f"(c[1]), "+f"(c[2]), "+f"(c[3])
                 : "r"(a[0]), "r"(a[1]), "r"(a[2]), "r"(a[3]), "r"(b0), "r"(b1));
}
__device__ __forceinline__ void bar_arrive(unsigned int* p) {
    asm volatile("red.add.release.gpu.u32 [%0], 1;" :: "l"(p) : "memory");
}
__device__ __forceinline__ uint32_t bar_ld(unsigned int* p) {
    uint32_t v;
    asm volatile("ld.acquire.gpu.u32 %0, [%1];" : "=r"(v) : "l"(p) : "memory");
    return v;
}
__device__ __forceinline__ uint32_t pack_bf16x2(float a, float b) {
    __nv_bfloat16 ha = __float2bfloat16(a), hb = __float2bfloat16(b);
    return (uint32_t)__bfloat16_as_ushort(ha) | ((uint32_t)__bfloat16_as_ushort(hb) << 16);
}
#define LDG64CG(v, p) \
    asm volatile("ld.global.cg.v2.u32 {%0,%1}, [%2];" : "=r"((v).x), "=r"((v).y) : "l"(p))

// ---------------- init ----------------
__global__ void init_kernel() {
    int i = blockIdx.x * blockDim.x + threadIdx.x;
    if (i < 8 * 32) { g_barA[i] = 0u; g_barB[i] = 0u; }
    // zero all h buffers: 2 arrays x 2 bufs x 131072 bf16 = 1MB = 65536 uint4
    if (i < 32768) {
        ((uint4*)g_hhi)[i] = make_uint4(0,0,0,0);
        ((uint4*)g_hlo)[i] = make_uint4(0,0,0,0);
    }
}

// ---------------- xs GEMM: m64 x n64 tiles, 2 CTAs/SM (proven) ----------------
#define X2ROWB 272
#define X2_AHI 0
#define X2_ALO 17408
#define X2_WHI 34816
#define X2_WLO 52224
#define SMEM_X2 69632

__global__ __launch_bounds__(256, 2)
void xs_mma_kernel(const float* __restrict__ x, const float* __restrict__ W_ih,
                   const float* __restrict__ b_ih, const float* __restrict__ b_hh) {
    extern __shared__ unsigned char smem[];
    const uint32_t sb = smem_u32(smem);
    const int tid = threadIdx.x;
    const int wid = tid >> 5, lane = tid & 31;
    const int m0 = blockIdx.y * 64;
    const int n0 = blockIdx.x * 64;
    const int tt = m0 >> 8;
    const int b0 = m0 & 255;

    {
        int r = tid >> 2, seg = (tid & 3) * 32;
        const float4* src = (const float4*)(x + ((size_t)(b0 + r) * Tn + tt) * In + seg);
        uint32_t dhi = sb + X2_AHI + r * X2ROWB + seg * 2;
        uint32_t dlo = sb + X2_ALO + r * X2ROWB + seg * 2;
        #pragma unroll
        for (int q = 0; q < 8; q++) {
            float4 v = src[q];
            __nv_bfloat16 h0 = __float2bfloat16(v.x), h1 = __float2bfloat16(v.y);
            __nv_bfloat16 h2 = __float2bfloat16(v.z), h3 = __float2bfloat16(v.w);
            uint32_t hi0 = (uint32_t)__bfloat16_as_ushort(h0) | ((uint32_t)__bfloat16_as_ushort(h1) << 16);
            uint32_t hi1 = (uint32_t)__bfloat16_as_ushort(h2) | ((uint32_t)__bfloat16_as_ushort(h3) << 16);
            uint32_t lo0 = pack_bf16x2(v.x - __bfloat162float(h0), v.y - __bfloat162float(h1));
            uint32_t lo1 = pack_bf16x2(v.z - __bfloat162float(h2), v.w - __bfloat162float(h3));
            asm volatile("st.shared.v2.b32 [%0], {%1,%2};" :: "r"(dhi + q * 8), "r"(hi0), "r"(hi1));
            asm volatile("st.shared.v2.b32 [%0], {%1,%2};" :: "r"(dlo + q * 8), "r"(lo0), "r"(lo1));
        }
    }
    {
        int r = tid >> 2, seg = (tid & 3) * 32;
        const float4* src = (const float4*)(W_ih + (size_t)(n0 + r) * In + seg);
        uint32_t dhi = sb + X2_WHI + r * X2ROWB + seg * 2;
        uint32_t dlo = sb + X2_WLO + r * X2ROWB + seg * 2;
        #pragma unroll
        for (int q = 0; q < 8; q++) {
            float4 v = src[q];
            __nv_bfloat16 h0 = __float2bfloat16(v.x), h1 = __float2bfloat16(v.y);
            __nv_bfloat16 h2 = __float2bfloat16(v.z), h3 = __float2bfloat16(v.w);
            uint32_t hi0 = (uint32_t)__bfloat16_as_ushort(h0) | ((uint32_t)__bfloat16_as_ushort(h1) << 16);
            uint32_t hi1 = (uint32_t)__bfloat16_as_ushort(h2) | ((uint32_t)__bfloat16_as_ushort(h3) << 16);
            uint32_t lo0 = pack_bf16x2(v.x - __bfloat162float(h0), v.y - __bfloat162float(h1));
            uint32_t lo1 = pack_bf16x2(v.z - __bfloat162float(h2), v.w - __bfloat162float(h3));
            asm volatile("st.shared.v2.b32 [%0], {%1,%2};" :: "r"(dhi + q * 8), "r"(hi0), "r"(hi1));
            asm volatile("st.shared.v2.b32 [%0], {%1,%2};" :: "r"(dlo + q * 8), "r"(lo0), "r"(lo1));
        }
    }
    __syncthreads();

    const int wm = wid & 3, wn = wid >> 2;
    const int ja = lane >> 3, ra = lane & 7;
    const int gq = lane >> 2, tq = lane & 3;

    const uint32_t a_off = (uint32_t)(wm * 16 + (ja & 1) * 8 + ra) * X2ROWB + (uint32_t)(ja >> 1) * 16;
    uint32_t w_off[2];
    #pragma unroll
    for (int np = 0; np < 2; np++)
        w_off[np] = (uint32_t)(wn * 32 + np * 16 + (ja >> 1) * 8 + ra) * X2ROWB + (uint32_t)(ja & 1) * 16;

    float c[4][4];
    #pragma unroll
    for (int j = 0; j < 4; j++)
        #pragma unroll
        for (int q = 0; q < 4; q++) c[j][q] = 0.f;

    #pragma unroll
    for (int ks = 0; ks < 8; ks++) {
        uint32_t kb = (uint32_t)ks * 32;
        uint32_t ahi[4], alo[4], whi[2][4], wlo[2][4];
        ldsm4(ahi, sb + X2_AHI + a_off + kb);
        ldsm4(alo, sb + X2_ALO + a_off + kb);
        #pragma unroll
        for (int np = 0; np < 2; np++) {
            ldsm4(whi[np], sb + X2_WHI + w_off[np] + kb);
            ldsm4(wlo[np], sb + X2_WLO + w_off[np] + kb);
        }
        #pragma unroll
        for (int nt = 0; nt < 4; nt++) {
            int np = nt >> 1, h = (nt & 1) * 2;
            mma_bf16(c[nt], ahi, whi[np][h], whi[np][h + 1]);
            mma_bf16(c[nt], ahi, wlo[np][h], wlo[np][h + 1]);
            mma_bf16(c[nt], alo, whi[np][h], whi[np][h + 1]);
        }
    }

    __syncthreads();
    #pragma unroll
    for (int nt = 0; nt < 4; nt++) {
        int cl = wn * 32 + nt * 8 + tq * 2;
        int col = n0 + cl;
        float ba = b_ih[col] + b_hh[col];
        float bb = b_ih[col + 1] + b_hh[col + 1];
        int rl = wm * 16 + gq;
        asm volatile("st.shared.v2.f32 [%0], {%1,%2};"
            :: "r"(sb + rl * X2ROWB + cl * 4), "f"(c[nt][0] + ba), "f"(c[nt][1] + bb));
        asm volatile("st.shared.v2.f32 [%0], {%1,%2};"
            :: "r"(sb + (rl + 8) * X2ROWB + cl * 4), "f"(c[nt][2] + ba), "f"(c[nt][3] + bb));
    }
    __syncthreads();
    for (int i = tid; i < 1024; i += 256) {
        int r = i >> 4, cc = (i & 15) * 4;
        uint32_t v0, v1, v2, v3;
        asm volatile("ld.shared.v4.b32 {%0,%1,%2,%3}, [%4];"
            : "=r"(v0), "=r"(v1), "=r"(v2), "=r"(v3) : "r"(sb + r * X2ROWB + cc * 4));
        *(uint4*)(g_xs + (size_t)(m0 + r) * Hn + n0 + cc) = make_uint4(v0, v1, v2, v3);
    }
}

// ---------------- persistent recurrence: W in regs, A via LDG.cg, no smem mainloop ----------------
// 8 warps = (wm:2 m16) x (ch:4 k128-chunks). B frags n32 x k128 hi/lo in 128 regs/thread.
// Custom k-permutation: lane tq's frag k-positions map to physical cols 4tq..4tq+3
// (consistent between A loads and B register init -> dot products exact).
__global__ __launch_bounds__(256, 1)
void rnn_persist(const float* __restrict__ W_hh) {
    __shared__ float sred[8 * 32 * 17];   // [wm*4+ch][cc 32][r 16], stride 17
    const int tid = threadIdx.x, wid = tid >> 5, lane = tid & 31;
    const int cta_m = blockIdx.x >> 4, cta_n = blockIdx.x & 15;
    const int m0 = cta_m * 32, n0 = cta_n * 32;
    unsigned int* barOut = (cta_n < 8) ? &g_barA[cta_m * 32] : &g_barB[cta_m * 32];
    const int wm = wid & 1, ch = wid >> 1;
    unsigned int* barIn = (ch < 2) ? &g_barA[cta_m * 32] : &g_barB[cta_m * 32];
    const int gq = lane >> 2, tq = lane & 3;
    const int r0 = m0 + wm * 16 + gq;
    const int kbase = ch * 128;

    // --- B registers: W_hh rows n0..n0+31 (B is n x k), this warp's k-chunk, hi/lo ---
    uint32_t Bh[4][8][2], Bl[4][8][2];
    #pragma unroll
    for (int g = 0; g < 4; g++) {
        int n = n0 + g * 8 + gq;
        #pragma unroll
        for (int j = 0; j < 8; j++) {
            float4 w = *(const float4*)(W_hh + (size_t)n * Hn + kbase + j * 16 + tq * 4);
            __nv_bfloat16 h0 = __float2bfloat16(w.x), h1 = __float2bfloat16(w.y);
            __nv_bfloat16 h2 = __float2bfloat16(w.z), h3 = __float2bfloat16(w.w);
            Bh[g][j][0] = (uint32_t)__bfloat16_as_ushort(h0) | ((uint32_t)__bfloat16_as_ushort(h1) << 16);
            Bh[g][j][1] = (uint32_t)__bfloat16_as_ushort(h2) | ((uint32_t)__bfloat16_as_ushort(h3) << 16);
            Bl[g][j][0] = pack_bf16x2(w.x - __bfloat162float(h0), w.y - __bfloat162float(h1));
            Bl[g][j][1] = pack_bf16x2(w.z - __bfloat162float(h2), w.w - __bfloat162float(h3));
        }
    }

    // epilogue constants: each thread owns 4 cols of one output row
    const int erow = wid * 4 + (lane >> 3);     // 0..31
    const int ecol = (lane & 7) * 4;            // 0..28
    const int ewm = erow >> 4, er = erow & 15;

    for (int t = 0; t < Tn; t++) {
        const int rb = t & 1, wb = rb ^ 1;
        const __nv_bfloat16* hh = g_hhi[rb];
        const __nv_bfloat16* hl = g_hlo[rb];

        // wait for this chunk's producers (all lanes poll; broadcast read)
        {
            unsigned int target = (unsigned int)t * 64u;
            while (bar_ld(barIn) < target) { }
        }

        const char* p0h = (const char*)(hh + (size_t)r0 * Hn) + kbase * 2 + tq * 8;
        const char* p1h = p0h + 8 * Hn * 2;
        const char* p0l = (const char*)(hl + (size_t)r0 * Hn) + kbase * 2 + tq * 8;
        const char* p1l = p0l + 8 * Hn * 2;

        float acc[4][4];
        #pragma unroll
        for (int g = 0; g < 4; g++)
            #pragma unroll
            for (int q = 0; q < 4; q++) acc[g][q] = 0.f;

        uint2 c0h, c1h, c0l, c1l, q0h, q1h, q0l, q1l;
        LDG64CG(c0h, p0h); LDG64CG(c1h, p1h);
        LDG64CG(c0l, p0l); LDG64CG(c1l, p1l);
        #pragma unroll
        for (int j = 0; j < 8; j++) {
            if (j < 7) {
                LDG64CG(q0h, p0h + (j + 1) * 32); LDG64CG(q1h, p1h + (j + 1) * 32);
                LDG64CG(q0l, p0l + (j + 1) * 32); LDG64CG(q1l, p1l + (j + 1) * 32);
            }
            uint32_t afh[4] = { c0h.x, c1h.x, c0h.y, c1h.y };
            uint32_t afl[4] = { c0l.x, c1l.x, c0l.y, c1l.y };
            #pragma unroll
            for (int g = 0; g < 4; g++) {
                mma_bf16(acc[g], afh, Bh[g][j][0], Bh[g][j][1]);
                mma_bf16(acc[g], afh, Bl[g][j][0], Bl[g][j][1]);
                mma_bf16(acc[g], afl, Bh[g][j][0], Bh[g][j][1]);
            }
            if (j < 7) { c0h = q0h; c1h = q1h; c0l = q0l; c1l = q1l; }
        }

        // k-partial reduction via smem
        __syncthreads();
        #pragma unroll
        for (int g = 0; g < 4; g++)
            #pragma unroll
            for (int q = 0; q < 4; q++) {
                int r = gq + (q >> 1) * 8;
                int cc = g * 8 + tq * 2 + (q & 1);
                sred[((wm * 4 + ch) * 32 + cc) * 17 + r] = acc[g][q];
            }
        __syncthreads();

        // reduce 4 chunks + tanh + write h (hi/lo) directly to global
        const float* xs_t = g_xs + (size_t)t * (Bsz * Hn) + (size_t)(m0 + erow) * Hn + n0 + ecol;
        float4 xv = *(const float4*)xs_t;
        float v0, v1, v2, v3;
        {
            int base = (ewm * 4) * 32;
            float s0 = sred[((base + 0 * 32) + ecol + 0) * 17 + er] + sred[((base + 1 * 32) + ecol + 0) * 17 + er]
                     + sred[((base + 2 * 32) + ecol + 0) * 17 + er] + sred[((base + 3 * 32) + ecol + 0) * 17 + er];
            float s1 = sred[((base + 0 * 32) + ecol + 1) * 17 + er] + sred[((base + 1 * 32) + ecol + 1) * 17 + er]
                     + sred[((base + 2 * 32) + ecol + 1) * 17 + er] + sred[((base + 3 * 32) + ecol + 1) * 17 + er];
            float s2 = sred[((base + 0 * 32) + ecol + 2) * 17 + er] + sred[((base + 1 * 32) + ecol + 2) * 17 + er]
                     + sred[((base + 2 * 32) + ecol + 2) * 17 + er] + sred[((base + 3 * 32) + ecol + 2) * 17 + er];
            float s3 = sred[((base + 0 * 32) + ecol + 3) * 17 + er] + sred[((base + 1 * 32) + ecol + 3) * 17 + er]
                     + sred[((base + 2 * 32) + ecol + 3) * 17 + er] + sred[((base + 3 * 32) + ecol + 3) * 17 + er];
            v0 = tanhf(s0 + xv.x); v1 = tanhf(s1 + xv.y);
            v2 = tanhf(s2 + xv.z); v3 = tanhf(s3 + xv.w);
        }
        {
            __nv_bfloat16 h0 = __float2bfloat16(v0), h1 = __float2bfloat16(v1);
            __nv_bfloat16 h2 = __float2bfloat16(v2), h3 = __float2bfloat16(v3);
            uint32_t wh0 = (uint32_t)__bfloat16_as_ushort(h0) | ((uint32_t)__bfloat16_as_ushort(h1) << 16);
            uint32_t wh1 = (uint32_t)__bfloat16_as_ushort(h2) | ((uint32_t)__bfloat16_as_ushort(h3) << 16);
            uint32_t wl0 = pack_bf16x2(v0 - __bfloat162float(h0), v1 - __bfloat162float(h1));
            uint32_t wl1 = pack_bf16x2(v2 - __bfloat162float(h2), v3 - __bfloat162float(h3));
            size_t off = (size_t)(m0 + erow) * Hn + n0 + ecol;
            *(uint2*)((__nv_bfloat16*)g_hhi[wb] + off) = make_uint2(wh0, wh1);
            *(uint2*)((__nv_bfloat16*)g_hlo[wb] + off) = make_uint2(wl0, wl1);
            if (t == Tn - 1)
                *(float4*)(g_hT + off) = make_float4(v0, v1, v2, v3);
        }

        // publish: drain this thread's stores, then one release-arrive per warp
        __threadfence();
        if (lane == 0) bar_arrive(barOut);
    }
}

// ---------------- final FC ----------------
__global__ void fc_kernel(const float* __restrict__ fc_w, const float* __restrict__ fc_b,
                          float* __restrict__ out) {
    int b = blockIdx.x;
    float acc = 0.f;
    for (int k = threadIdx.x; k < Hn; k += 128)
        acc += g_hT[b * Hn + k] * fc_w[k];
    __shared__ float s[128];
    s[threadIdx.x] = acc;
    __syncthreads();
    #pragma unroll
    for (int o = 64; o > 0; o >>= 1) {
        if (threadIdx.x < o) s[threadIdx.x] += s[threadIdx.x + o];
        __syncthreads();
    }
    if (threadIdx.x == 0) out[b] = s[0] + fc_b[0];
}

extern "C" void kernel_launch(void* const* d_in, const int* in_sizes, int n_in,
                              void* d_out, int out_size) {
    const float* x    = (const float*)d_in[0];
    const float* W_ih = (const float*)d_in[1];
    const float* W_hh = (const float*)d_in[2];
    const float* b_ih = (const float*)d_in[3];
    const float* b_hh = (const float*)d_in[4];
    const float* fc_w = (const float*)d_in[5];
    const float* fc_b = (const float*)d_in[6];
    float* out = (float*)d_out;

    cudaFuncSetAttribute(xs_mma_kernel, cudaFuncAttributeMaxDynamicSharedMemorySize, SMEM_X2);

    init_kernel<<<256, 256>>>();
    dim3 gx(Hn / 64, (Tn * Bsz) / 64);   // (8, 1024)
    xs_mma_kernel<<<gx, 256, SMEM_X2>>>(x, W_ih, b_ih, b_hh);
    rnn_persist<<<NCTA, 256>>>(W_hh);
    fc_kernel<<<Bsz, 128>>>(fc_w, fc_b, out);
}

// round 10
// speedup vs baseline: 1.0368x; 1.0368x over previous
#include <cuda_runtime.h>
#include <cuda_bf16.h>
#include <math.h>
#include <stdint.h>

#define Bsz 256
#define Tn  256
#define In  128
#define Hn  512
#define NCTA 64

// ---------------- device scratch ----------------
__device__ float g_xs[(size_t)Tn * Bsz * Hn];
// swizzled h images: [buf][group mg: 8][kc: 2][row: 32][512B]
__device__ uint4 g_ihi4[2][16384];
__device__ uint4 g_ilo4[2][16384];
__device__ float g_hT[Bsz * Hn];

// ---------------- helpers ----------------
__device__ __forceinline__ uint32_t smem_u32(const void* p) {
    uint32_t a;
    asm("{ .reg .u64 t; cvta.to.shared.u64 t, %1; cvt.u32.u64 %0, t; }" : "=r"(a) : "l"(p));
    return a;
}
#define MBI(addr, cnt) asm volatile("mbarrier.init.shared.b64 [%0], %1;" :: "r"(addr), "r"(cnt) : "memory")
#define MBTX(addr, bytes) asm volatile("mbarrier.arrive.expect_tx.shared.b64 _, [%0], %1;" :: "r"(addr), "r"(bytes) : "memory")
#define MBW(addr, par) do { \
    asm volatile("{\n\t.reg .pred P1;\n\tWL_%=:\n\t" \
        "mbarrier.try_wait.parity.acquire.cta.shared::cta.b64 P1, [%0], %1, 0x989680;\n\t" \
        "@P1 bra.uni WD_%=;\n\tbra.uni WL_%=;\n\tWD_%=:\n\t}" \
        :: "r"((uint32_t)(addr)), "r"((uint32_t)(par)) : "memory"); } while (0)
#define MB_ARRIVE_REMOTE(local_addr, rank) \
    asm volatile("{\n\t.reg .b32 ra;\n\t" \
        "mapa.shared::cluster.u32 ra, %0, %1;\n\t" \
        "mbarrier.arrive.shared::cluster.b64 _, [ra];\n\t}" \
        :: "r"((uint32_t)(local_addr)), "r"((uint32_t)(rank)) : "memory")

__device__ __forceinline__ void bulk_g2s(uint32_t dst, const void* src, uint32_t bytes, uint32_t mbar) {
    asm volatile("cp.async.bulk.shared::cta.global.mbarrier::complete_tx::bytes [%0], [%1], %2, [%3];"
        :: "r"(dst), "l"(src), "r"(bytes), "r"(mbar) : "memory");
}
__device__ __forceinline__ void ldsm4(uint32_t r[4], uint32_t addr) {
    asm volatile("ldmatrix.sync.aligned.m8n8.x4.shared.b16 {%0,%1,%2,%3}, [%4];"
                 : "=r"(r[0]), "=r"(r[1]), "=r"(r[2]), "=r"(r[3]) : "r"(addr));
}
__device__ __forceinline__ void mma_bf16(float c[4], const uint32_t a[4], uint32_t b0, uint32_t b1) {
    asm volatile("mma.sync.aligned.m16n8k16.row.col.f32.bf16.bf16.f32 "
                 "{%0,%1,%2,%3},{%4,%5,%6,%7},{%8,%9},{%0,%1,%2,%3};"
                 : "+f"(c[0]), "+f"(c[1]), "+f"(c[2]), "+f"(c[3])
                 : "r"(a[0]), "r"(a[1]), "r"(a[2]), "r"(a[3]), "r"(b0), "r"(b1));
}
__device__ __forceinline__ uint32_t pack_bf16x2(float a, float b) {
    __nv_bfloat16 ha = __float2bfloat16(a), hb = __float2bfloat16(b);
    return (uint32_t)__bfloat16_as_ushort(ha) | ((uint32_t)__bfloat16_as_ushort(hb) << 16);
}

// ---------------- init ----------------
__global__ void init_kernel() {
    int i = blockIdx.x * blockDim.x + threadIdx.x;
    if (i < 16384) {
        g_ihi4[0][i] = make_uint4(0,0,0,0); g_ihi4[1][i] = make_uint4(0,0,0,0);
        g_ilo4[0][i] = make_uint4(0,0,0,0); g_ilo4[1][i] = make_uint4(0,0,0,0);
    }
}

// ---------------- xs GEMM: m64 x n64 tiles, 2 CTAs/SM (proven round-8) ----------------
#define X2ROWB 272
#define X2_AHI 0
#define X2_ALO 17408
#define X2_WHI 34816
#define X2_WLO 52224
#define SMEM_X2 69632

__global__ __launch_bounds__(256, 2)
void xs_mma_kernel(const float* __restrict__ x, const float* __restrict__ W_ih,
                   const float* __restrict__ b_ih, const float* __restrict__ b_hh) {
    extern __shared__ unsigned char smem[];
    const uint32_t sb = smem_u32(smem);
    const int tid = threadIdx.x;
    const int wid = tid >> 5, lane = tid & 31;
    const int m0 = blockIdx.y * 64;
    const int n0 = blockIdx.x * 64;
    const int tt = m0 >> 8;
    const int b0 = m0 & 255;

    {
        int r = tid >> 2, seg = (tid & 3) * 32;
        const float4* src = (const float4*)(x + ((size_t)(b0 + r) * Tn + tt) * In + seg);
        uint32_t dhi = sb + X2_AHI + r * X2ROWB + seg * 2;
        uint32_t dlo = sb + X2_ALO + r * X2ROWB + seg * 2;
        #pragma unroll
        for (int q = 0; q < 8; q++) {
            float4 v = src[q];
            __nv_bfloat16 h0 = __float2bfloat16(v.x), h1 = __float2bfloat16(v.y);
            __nv_bfloat16 h2 = __float2bfloat16(v.z), h3 = __float2bfloat16(v.w);
            uint32_t hi0 = (uint32_t)__bfloat16_as_ushort(h0) | ((uint32_t)__bfloat16_as_ushort(h1) << 16);
            uint32_t hi1 = (uint32_t)__bfloat16_as_ushort(h2) | ((uint32_t)__bfloat16_as_ushort(h3) << 16);
            uint32_t lo0 = pack_bf16x2(v.x - __bfloat162float(h0), v.y - __bfloat162float(h1));
            uint32_t lo1 = pack_bf16x2(v.z - __bfloat162float(h2), v.w - __bfloat162float(h3));
            asm volatile("st.shared.v2.b32 [%0], {%1,%2};" :: "r"(dhi + q * 8), "r"(hi0), "r"(hi1));
            asm volatile("st.shared.v2.b32 [%0], {%1,%2};" :: "r"(dlo + q * 8), "r"(lo0), "r"(lo1));
        }
    }
    {
        int r = tid >> 2, seg = (tid & 3) * 32;
        const float4* src = (const float4*)(W_ih + (size_t)(n0 + r) * In + seg);
        uint32_t dhi = sb + X2_WHI + r * X2ROWB + seg * 2;
        uint32_t dlo = sb + X2_WLO + r * X2ROWB + seg * 2;
        #pragma unroll
        for (int q = 0; q < 8; q++) {
            float4 v = src[q];
            __nv_bfloat16 h0 = __float2bfloat16(v.x), h1 = __float2bfloat16(v.y);
            __nv_bfloat16 h2 = __float2bfloat16(v.z), h3 = __float2bfloat16(v.w);
            uint32_t hi0 = (uint32_t)__bfloat16_as_ushort(h0) | ((uint32_t)__bfloat16_as_ushort(h1) << 16);
            uint32_t hi1 = (uint32_t)__bfloat16_as_ushort(h2) | ((uint32_t)__bfloat16_as_ushort(h3) << 16);
            uint32_t lo0 = pack_bf16x2(v.x - __bfloat162float(h0), v.y - __bfloat162float(h1));
            uint32_t lo1 = pack_bf16x2(v.z - __bfloat162float(h2), v.w - __bfloat162float(h3));
            asm volatile("st.shared.v2.b32 [%0], {%1,%2};" :: "r"(dhi + q * 8), "r"(hi0), "r"(hi1));
            asm volatile("st.shared.v2.b32 [%0], {%1,%2};" :: "r"(dlo + q * 8), "r"(lo0), "r"(lo1));
        }
    }
    __syncthreads();

    const int wm = wid & 3, wn = wid >> 2;
    const int ja = lane >> 3, ra = lane & 7;
    const int gq = lane >> 2, tq = lane & 3;

    const uint32_t a_off = (uint32_t)(wm * 16 + (ja & 1) * 8 + ra) * X2ROWB + (uint32_t)(ja >> 1) * 16;
    uint32_t w_off[2];
    #pragma unroll
    for (int np = 0; np < 2; np++)
        w_off[np] = (uint32_t)(wn * 32 + np * 16 + (ja >> 1) * 8 + ra) * X2ROWB + (uint32_t)(ja & 1) * 16;

    float c[4][4];
    #pragma unroll
    for (int j = 0; j < 4; j++)
        #pragma unroll
        for (int q = 0; q < 4; q++) c[j][q] = 0.f;

    #pragma unroll
    for (int ks = 0; ks < 8; ks++) {
        uint32_t kb = (uint32_t)ks * 32;
        uint32_t ahi[4], alo[4], whi[2][4], wlo[2][4];
        ldsm4(ahi, sb + X2_AHI + a_off + kb);
        ldsm4(alo, sb + X2_ALO + a_off + kb);
        #pragma unroll
        for (int np = 0; np < 2; np++) {
            ldsm4(whi[np], sb + X2_WHI + w_off[np] + kb);
            ldsm4(wlo[np], sb + X2_WLO + w_off[np] + kb);
        }
        #pragma unroll
        for (int nt = 0; nt < 4; nt++) {
            int np = nt >> 1, h = (nt & 1) * 2;
            mma_bf16(c[nt], ahi, whi[np][h], whi[np][h + 1]);
            mma_bf16(c[nt], ahi, wlo[np][h], wlo[np][h + 1]);
            mma_bf16(c[nt], alo, whi[np][h], whi[np][h + 1]);
        }
    }

    __syncthreads();
    #pragma unroll
    for (int nt = 0; nt < 4; nt++) {
        int cl = wn * 32 + nt * 8 + tq * 2;
        int col = n0 + cl;
        float ba = b_ih[col] + b_hh[col];
        float bb = b_ih[col + 1] + b_hh[col + 1];
        int rl = wm * 16 + gq;
        asm volatile("st.shared.v2.f32 [%0], {%1,%2};"
            :: "r"(sb + rl * X2ROWB + cl * 4), "f"(c[nt][0] + ba), "f"(c[nt][1] + bb));
        asm volatile("st.shared.v2.f32 [%0], {%1,%2};"
            :: "r"(sb + (rl + 8) * X2ROWB + cl * 4), "f"(c[nt][2] + ba), "f"(c[nt][3] + bb));
    }
    __syncthreads();
    for (int i = tid; i < 1024; i += 256) {
        int r = i >> 4, cc = (i & 15) * 4;
        uint32_t v0, v1, v2, v3;
        asm volatile("ld.shared.v4.b32 {%0,%1,%2,%3}, [%4];"
            : "=r"(v0), "=r"(v1), "=r"(v2), "=r"(v3) : "r"(sb + r * X2ROWB + cc * 4));
        *(uint4*)(g_xs + (size_t)(m0 + r) * Hn + n0 + cc) = make_uint4(v0, v1, v2, v3);
    }
}

// ---------------- persistent recurrence: 8-CTA clusters, DSMEM step barrier ----------------
// 64 CTAs: mg = blockIdx.x>>3 (m-group, cluster), nt = blockIdx.x&7 (n64 tile).
// 288 threads: 8 MMA warps (wm2 x wn4, m16n16) + 1 DMA warp.
// SMEM: mbarriers @0 (full0@0 full1@8 peers0@16 peers1@24); W hi/lo; A hi/lo (bulk images).
#define ROWB 1040
#define OFF_WHI 1024
#define OFF_WLO 67584
#define OFF_AHI 134144
#define OFF_ALO 166912
#define SMEM_RP 199680

__global__ __launch_bounds__(288, 1) __cluster_dims__(8, 1, 1)
void rnn_persist(const float* __restrict__ W_hh) {
    extern __shared__ unsigned char smem[];
    const uint32_t sb = smem_u32(smem);
    const int tid = threadIdx.x, wid = tid >> 5, lane = tid & 31;
    const int mg = blockIdx.x >> 3, nt = blockIdx.x & 7;
    const int m0 = mg * 32, n0 = nt * 64;
    const int half = nt >> 2;                  // cols [n0,+64) live in kc half (n0>>8)

    // W tile rows [n0, +64), all k, hi/lo (resident all 256 steps)
    for (int idx = tid; idx < 64 * 512; idx += 288) {
        int r = idx >> 9, k = idx & 511;
        float w = W_hh[(size_t)(n0 + r) * Hn + k];
        __nv_bfloat16 hi = __float2bfloat16(w);
        __nv_bfloat16 lo = __float2bfloat16(w - __bfloat162float(hi));
        *(__nv_bfloat16*)(smem + OFF_WHI + r * ROWB + k * 2) = hi;
        *(__nv_bfloat16*)(smem + OFF_WLO + r * ROWB + k * 2) = lo;
    }
    if (tid == 0) {
        MBI(sb + 0, 1);  MBI(sb + 8, 1);    // full0/full1 (tx-based)
        MBI(sb + 16, 4); MBI(sb + 24, 4);   // peers0/peers1 (4 producers per half)
    }
    __syncthreads();
    asm volatile("barrier.cluster.arrive.aligned;" ::: "memory");
    asm volatile("barrier.cluster.wait.aligned;" ::: "memory");

    // MMA lane constants (wid < 8)
    const int wm = wid & 1, wn = wid >> 1;
    const int gq = lane >> 2, tq = lane & 3;
    const int ja = lane >> 3, ra = lane & 7;
    const int r0 = m0 + wm * 16 + gq;
    const int r1 = r0 + 8;
    const int r_loc = wm * 16 + (ja & 1) * 8 + ra;
    const uint32_t a_rowbase = (uint32_t)r_loc * 512;
    const uint32_t rl = (uint32_t)(r_loc & 7);
    const uint32_t uo = (uint32_t)(ja >> 1);
    const uint32_t b_off = (uint32_t)(wn * 16 + (ja >> 1) * 8 + ra) * ROWB + (uint32_t)(ja & 1) * 16;
    const int col0 = n0 + wn * 16 + tq * 2;
    const int rle0 = wm * 16 + gq;
    unsigned char* const img_hi_base = (unsigned char*)g_ihi4;
    unsigned char* const img_lo_base = (unsigned char*)g_ilo4;
    const size_t grp_off = (size_t)mg * 32768;

    for (int t = 0; t < Tn; t++) {
        const int rb = t & 1, wb = rb ^ 1;

        if (wid == 8) {
            if (lane == 0) {
                const unsigned char* shi = (const unsigned char*)g_ihi4[rb] + grp_off;
                const unsigned char* slo = (const unsigned char*)g_ilo4[rb] + grp_off;
                if (t > 0) MBW(sb + 16, (t - 1) & 1);          // kc0 producers done
                MBTX(sb + 0, 32768u);
                bulk_g2s(sb + OFF_AHI, shi, 16384u, sb + 0);
                bulk_g2s(sb + OFF_ALO, slo, 16384u, sb + 0);
                if (t > 0) MBW(sb + 24, (t - 1) & 1);          // kc1 producers done
                MBTX(sb + 8, 32768u);
                bulk_g2s(sb + OFF_AHI + 16384, shi + 16384, 16384u, sb + 8);
                bulk_g2s(sb + OFF_ALO + 16384, slo + 16384, 16384u, sb + 8);
            }
        } else {
            const float* xs_t = g_xs + (size_t)t * (Bsz * Hn);
            float2 xv[2][2];
            #pragma unroll
            for (int n2 = 0; n2 < 2; n2++) {
                xv[n2][0] = *(const float2*)(xs_t + (size_t)r0 * Hn + col0 + n2 * 8);
                xv[n2][1] = *(const float2*)(xs_t + (size_t)r1 * Hn + col0 + n2 * 8);
            }

            float c[2][4];
            #pragma unroll
            for (int i = 0; i < 2; i++)
                #pragma unroll
                for (int j = 0; j < 4; j++) c[i][j] = 0.f;

            #pragma unroll
            for (int kc = 0; kc < 2; kc++) {
                MBW(sb + 8 * kc, t & 1);
                #pragma unroll 8
                for (int ks2 = 0; ks2 < 16; ks2++) {
                    uint32_t u = ((uint32_t)ks2 << 1) | uo;
                    uint32_t u2 = (u & 24u) | ((u & 7u) ^ rl);
                    uint32_t aoff = ((uint32_t)kc << 14) + a_rowbase + (u2 << 4);
                    uint32_t kb = (uint32_t)(kc * 16 + ks2) * 32;
                    uint32_t ahi[4], alo[4], bhi[4], blo[4];
                    ldsm4(ahi, sb + OFF_AHI + aoff);
                    ldsm4(alo, sb + OFF_ALO + aoff);
                    ldsm4(bhi, sb + OFF_WHI + b_off + kb);
                    ldsm4(blo, sb + OFF_WLO + b_off + kb);
                    mma_bf16(c[0], ahi, bhi[0], bhi[1]);
                    mma_bf16(c[0], ahi, blo[0], blo[1]);
                    mma_bf16(c[0], alo, bhi[0], bhi[1]);
                    mma_bf16(c[1], ahi, bhi[2], bhi[3]);
                    mma_bf16(c[1], ahi, blo[2], blo[3]);
                    mma_bf16(c[1], alo, bhi[2], bhi[3]);
                }
            }

            unsigned char* ohi = img_hi_base + (size_t)wb * 262144 + grp_off;
            unsigned char* olo = img_lo_base + (size_t)wb * 262144 + grp_off;
            #pragma unroll
            for (int n2 = 0; n2 < 2; n2++) {
                int col = col0 + n2 * 8;
                int kc = col >> 8;
                uint32_t u = (uint32_t)((col & 255) >> 3);
                #pragma unroll
                for (int hf = 0; hf < 2; hf++) {
                    int rle = rle0 + hf * 8;
                    float s0 = tanhf(c[n2][hf * 2]     + xv[n2][hf].x);
                    float s1 = tanhf(c[n2][hf * 2 + 1] + xv[n2][hf].y);
                    __nv_bfloat16 h0 = __float2bfloat16(s0);
                    __nv_bfloat16 h1 = __float2bfloat16(s1);
                    uint32_t wh = (uint32_t)__bfloat16_as_ushort(h0) | ((uint32_t)__bfloat16_as_ushort(h1) << 16);
                    uint32_t wl = pack_bf16x2(s0 - __bfloat162float(h0), s1 - __bfloat162float(h1));
                    uint32_t u2 = (u & 24u) | ((u & 7u) ^ (uint32_t)(rle & 7));
                    uint32_t off = (uint32_t)kc * 16384u + (uint32_t)rle * 512u + (u2 << 4) + (uint32_t)(tq * 4);
                    *(uint32_t*)(ohi + off) = wh;
                    *(uint32_t*)(olo + off) = wl;
                    if (t == Tn - 1)
                        *(float2*)(g_hT + (size_t)(m0 + rle) * Hn + col) = make_float2(s0, s1);
                }
            }
        }

        __syncthreads();
        // signal: this CTA's half-slice of h(t+1) is published (skip on last step)
        if (tid == 0 && t < Tn - 1) {
            __threadfence();
            #pragma unroll
            for (int cr = 0; cr < 8; cr++)
                MB_ARRIVE_REMOTE(sb + 16 + half * 8, cr);
        }
    }
}

// ---------------- final FC ----------------
__global__ void fc_kernel(const float* __restrict__ fc_w, const float* __restrict__ fc_b,
                          float* __restrict__ out) {
    int b = blockIdx.x;
    float acc = 0.f;
    for (int k = threadIdx.x; k < Hn; k += 128)
        acc += g_hT[b * Hn + k] * fc_w[k];
    __shared__ float s[128];
    s[threadIdx.x] = acc;
    __syncthreads();
    #pragma unroll
    for (int o = 64; o > 0; o >>= 1) {
        if (threadIdx.x < o) s[threadIdx.x] += s[threadIdx.x + o];
        __syncthreads();
    }
    if (threadIdx.x == 0) out[b] = s[0] + fc_b[0];
}

extern "C" void kernel_launch(void* const* d_in, const int* in_sizes, int n_in,
                              void* d_out, int out_size) {
    const float* x    = (const float*)d_in[0];
    const float* W_ih = (const float*)d_in[1];
    const float* W_hh = (const float*)d_in[2];
    const float* b_ih = (const float*)d_in[3];
    const float* b_hh = (const float*)d_in[4];
    const float* fc_w = (const float*)d_in[5];
    const float* fc_b = (const float*)d_in[6];
    float* out = (float*)d_out;

    cudaFuncSetAttribute(xs_mma_kernel, cudaFuncAttributeMaxDynamicSharedMemorySize, SMEM_X2);
    cudaFuncSetAttribute(rnn_persist, cudaFuncAttributeMaxDynamicSharedMemorySize, SMEM_RP);

    init_kernel<<<64, 256>>>();
    dim3 gx(Hn / 64, (Tn * Bsz) / 64);   // (8, 1024)
    xs_mma_kernel<<<gx, 256, SMEM_X2>>>(x, W_ih, b_ih, b_hh);
    rnn_persist<<<NCTA, 288, SMEM_RP>>>(W_hh);
    fc_kernel<<<Bsz, 128>>>(fc_w, fc_b, out);
}

// round 11
// speedup vs baseline: 1.1385x; 1.0981x over previous
#include <cuda_runtime.h>
#include <cuda_bf16.h>
#include <math.h>
#include <stdint.h>

#define Bsz 256
#define Tn  256
#define In  128
#define Hn  512
#define NCTA 128

// ---------------- device scratch ----------------
__device__ float g_xs[(size_t)Tn * Bsz * Hn];
// swizzled h images: [buf][group mg: 8][kc: 2][row: 32][512B]
__device__ uint4 g_ihi4[2][16384];
__device__ uint4 g_ilo4[2][16384];
__device__ float g_hT[Bsz * Hn];
__device__ unsigned int g_barA[8 * 32];   // kc0 producers (n<8), padded
__device__ unsigned int g_barB[8 * 32];   // kc1 producers (n>=8)

// ---------------- helpers ----------------
__device__ __forceinline__ uint32_t smem_u32(const void* p) {
    uint32_t a;
    asm("{ .reg .u64 t; cvta.to.shared.u64 t, %1; cvt.u32.u64 %0, t; }" : "=r"(a) : "l"(p));
    return a;
}
#define MBI(addr, cnt) asm volatile("mbarrier.init.shared.b64 [%0], %1;" :: "r"(addr), "r"(cnt) : "memory")
#define MBTX(addr, bytes) asm volatile("mbarrier.arrive.expect_tx.shared.b64 _, [%0], %1;" :: "r"(addr), "r"(bytes) : "memory")
#define MBW(addr, par) do { \
    asm volatile("{\n\t.reg .pred P1;\n\tWL_%=:\n\t" \
        "mbarrier.try_wait.parity.acquire.cta.shared::cta.b64 P1, [%0], %1, 0x989680;\n\t" \
        "@P1 bra.uni WD_%=;\n\tbra.uni WL_%=;\n\tWD_%=:\n\t}" \
        :: "r"((uint32_t)(addr)), "r"((uint32_t)(par)) : "memory"); } while (0)

__device__ __forceinline__ void bulk_g2s(uint32_t dst, const void* src, uint32_t bytes, uint32_t mbar) {
    asm volatile("cp.async.bulk.shared::cta.global.mbarrier::complete_tx::bytes [%0], [%1], %2, [%3];"
        :: "r"(dst), "l"(src), "r"(bytes), "r"(mbar) : "memory");
}
__device__ __forceinline__ void ldsm4(uint32_t r[4], uint32_t addr) {
    asm volatile("ldmatrix.sync.aligned.m8n8.x4.shared.b16 {%0,%1,%2,%3}, [%4];"
                 : "=r"(r[0]), "=r"(r[1]), "=r"(r[2]), "=r"(r[3]) : "r"(addr));
}
__device__ __forceinline__ void mma_bf16(float c[4], const uint32_t a[4], uint32_t b0, uint32_t b1) {
    asm volatile("mma.sync.aligned.m16n8k16.row.col.f32.bf16.bf16.f32 "
                 "{%0,%1,%2,%3},{%4,%5,%6,%7},{%8,%9},{%0,%1,%2,%3};"
                 : "+f"(c[0]), "+f"(c[1]), "+f"(c[2]), "+f"(c[3])
                 : "r"(a[0]), "r"(a[1]), "r"(a[2]), "r"(a[3]), "r"(b0), "r"(b1));
}
__device__ __forceinline__ void bar_arrive(unsigned int* p) {
    asm volatile("red.add.release.gpu.u32 [%0], 1;" :: "l"(p) : "memory");
}
__device__ __forceinline__ uint32_t bar_ld(unsigned int* p) {
    uint32_t v;
    asm volatile("ld.acquire.gpu.u32 %0, [%1];" : "=r"(v) : "l"(p) : "memory");
    return v;
}
__device__ __forceinline__ uint32_t pack_bf16x2(float a, float b) {
    __nv_bfloat16 ha = __float2bfloat16(a), hb = __float2bfloat16(b);
    return (uint32_t)__bfloat16_as_ushort(ha) | ((uint32_t)__bfloat16_as_ushort(hb) << 16);
}
// fast tanh: 1 - 2/(e^{2x}+1). abs err ~1e-7; saturates to +-1 correctly.
__device__ __forceinline__ float ftanh(float x) {
    float e = __expf(2.0f * x);
    return 1.0f - __fdividef(2.0f, e + 1.0f);
}

// ---------------- init ----------------
__global__ void init_kernel() {
    int i = blockIdx.x * blockDim.x + threadIdx.x;
    if (i < 8 * 32) { g_barA[i] = 0u; g_barB[i] = 0u; }
    if (i < 16384) {
        g_ihi4[0][i] = make_uint4(0,0,0,0); g_ihi4[1][i] = make_uint4(0,0,0,0);
        g_ilo4[0][i] = make_uint4(0,0,0,0); g_ilo4[1][i] = make_uint4(0,0,0,0);
    }
}

// ---------------- xs GEMM: m64 x n64 tiles, 2 CTAs/SM (proven) ----------------
#define X2ROWB 272
#define X2_AHI 0
#define X2_ALO 17408
#define X2_WHI 34816
#define X2_WLO 52224
#define SMEM_X2 69632

__global__ __launch_bounds__(256, 2)
void xs_mma_kernel(const float* __restrict__ x, const float* __restrict__ W_ih,
                   const float* __restrict__ b_ih, const float* __restrict__ b_hh) {
    extern __shared__ unsigned char smem[];
    const uint32_t sb = smem_u32(smem);
    const int tid = threadIdx.x;
    const int wid = tid >> 5, lane = tid & 31;
    const int m0 = blockIdx.y * 64;
    const int n0 = blockIdx.x * 64;
    const int tt = m0 >> 8;
    const int b0 = m0 & 255;

    {
        int r = tid >> 2, seg = (tid & 3) * 32;
        const float4* src = (const float4*)(x + ((size_t)(b0 + r) * Tn + tt) * In + seg);
        uint32_t dhi = sb + X2_AHI + r * X2ROWB + seg * 2;
        uint32_t dlo = sb + X2_ALO + r * X2ROWB + seg * 2;
        #pragma unroll
        for (int q = 0; q < 8; q++) {
            float4 v = src[q];
            __nv_bfloat16 h0 = __float2bfloat16(v.x), h1 = __float2bfloat16(v.y);
            __nv_bfloat16 h2 = __float2bfloat16(v.z), h3 = __float2bfloat16(v.w);
            uint32_t hi0 = (uint32_t)__bfloat16_as_ushort(h0) | ((uint32_t)__bfloat16_as_ushort(h1) << 16);
            uint32_t hi1 = (uint32_t)__bfloat16_as_ushort(h2) | ((uint32_t)__bfloat16_as_ushort(h3) << 16);
            uint32_t lo0 = pack_bf16x2(v.x - __bfloat162float(h0), v.y - __bfloat162float(h1));
            uint32_t lo1 = pack_bf16x2(v.z - __bfloat162float(h2), v.w - __bfloat162float(h3));
            asm volatile("st.shared.v2.b32 [%0], {%1,%2};" :: "r"(dhi + q * 8), "r"(hi0), "r"(hi1));
            asm volatile("st.shared.v2.b32 [%0], {%1,%2};" :: "r"(dlo + q * 8), "r"(lo0), "r"(lo1));
        }
    }
    {
        int r = tid >> 2, seg = (tid & 3) * 32;
        const float4* src = (const float4*)(W_ih + (size_t)(n0 + r) * In + seg);
        uint32_t dhi = sb + X2_WHI + r * X2ROWB + seg * 2;
        uint32_t dlo = sb + X2_WLO + r * X2ROWB + seg * 2;
        #pragma unroll
        for (int q = 0; q < 8; q++) {
            float4 v = src[q];
            __nv_bfloat16 h0 = __float2bfloat16(v.x), h1 = __float2bfloat16(v.y);
            __nv_bfloat16 h2 = __float2bfloat16(v.z), h3 = __float2bfloat16(v.w);
            uint32_t hi0 = (uint32_t)__bfloat16_as_ushort(h0) | ((uint32_t)__bfloat16_as_ushort(h1) << 16);
            uint32_t hi1 = (uint32_t)__bfloat16_as_ushort(h2) | ((uint32_t)__bfloat16_as_ushort(h3) << 16);
            uint32_t lo0 = pack_bf16x2(v.x - __bfloat162float(h0), v.y - __bfloat162float(h1));
            uint32_t lo1 = pack_bf16x2(v.z - __bfloat162float(h2), v.w - __bfloat162float(h3));
            asm volatile("st.shared.v2.b32 [%0], {%1,%2};" :: "r"(dhi + q * 8), "r"(hi0), "r"(hi1));
            asm volatile("st.shared.v2.b32 [%0], {%1,%2};" :: "r"(dlo + q * 8), "r"(lo0), "r"(lo1));
        }
    }
    __syncthreads();

    const int wm = wid & 3, wn = wid >> 2;
    const int ja = lane >> 3, ra = lane & 7;
    const int gq = lane >> 2, tq = lane & 3;

    const uint32_t a_off = (uint32_t)(wm * 16 + (ja & 1) * 8 + ra) * X2ROWB + (uint32_t)(ja >> 1) * 16;
    uint32_t w_off[2];
    #pragma unroll
    for (int np = 0; np < 2; np++)
        w_off[np] = (uint32_t)(wn * 32 + np * 16 + (ja >> 1) * 8 + ra) * X2ROWB + (uint32_t)(ja & 1) * 16;

    float c[4][4];
    #pragma unroll
    for (int j = 0; j < 4; j++)
        #pragma unroll
        for (int q = 0; q < 4; q++) c[j][q] = 0.f;

    #pragma unroll
    for (int ks = 0; ks < 8; ks++) {
        uint32_t kb = (uint32_t)ks * 32;
        uint32_t ahi[4], alo[4], whi[2][4], wlo[2][4];
        ldsm4(ahi, sb + X2_AHI + a_off + kb);
        ldsm4(alo, sb + X2_ALO + a_off + kb);
        #pragma unroll
        for (int np = 0; np < 2; np++) {
            ldsm4(whi[np], sb + X2_WHI + w_off[np] + kb);
            ldsm4(wlo[np], sb + X2_WLO + w_off[np] + kb);
        }
        #pragma unroll
        for (int nt = 0; nt < 4; nt++) {
            int np = nt >> 1, h = (nt & 1) * 2;
            mma_bf16(c[nt], ahi, whi[np][h], whi[np][h + 1]);
            mma_bf16(c[nt], ahi, wlo[np][h], wlo[np][h + 1]);
            mma_bf16(c[nt], alo, whi[np][h], whi[np][h + 1]);
        }
    }

    __syncthreads();
    #pragma unroll
    for (int nt = 0; nt < 4; nt++) {
        int cl = wn * 32 + nt * 8 + tq * 2;
        int col = n0 + cl;
        float ba = b_ih[col] + b_hh[col];
        float bb = b_ih[col + 1] + b_hh[col + 1];
        int rl = wm * 16 + gq;
        asm volatile("st.shared.v2.f32 [%0], {%1,%2};"
            :: "r"(sb + rl * X2ROWB + cl * 4), "f"(c[nt][0] + ba), "f"(c[nt][1] + bb));
        asm volatile("st.shared.v2.f32 [%0], {%1,%2};"
            :: "r"(sb + (rl + 8) * X2ROWB + cl * 4), "f"(c[nt][2] + ba), "f"(c[nt][3] + bb));
    }
    __syncthreads();
    for (int i = tid; i < 1024; i += 256) {
        int r = i >> 4, cc = (i & 15) * 4;
        uint32_t v0, v1, v2, v3;
        asm volatile("ld.shared.v4.b32 {%0,%1,%2,%3}, [%4];"
            : "=r"(v0), "=r"(v1), "=r"(v2), "=r"(v3) : "r"(sb + r * X2ROWB + cc * 4));
        *(uint4*)(g_xs + (size_t)(m0 + r) * Hn + n0 + cc) = make_uint4(v0, v1, v2, v3);
    }
}

// ---------------- persistent recurrence: split-kc + split-hi/lo barriers, DMA warp ----------------
#define ROWB 1040
#define OFF_BAR 0          // hi0@0 lo0@8 hi1@16 lo1@24
#define OFF_WHI 1024
#define OFF_WLO 34304
#define OFF_AHI 67584
#define OFF_ALO 100352
#define SMEM_RP 133120

__global__ __launch_bounds__(160, 1)
void rnn_persist(const float* __restrict__ W_hh) {
    extern __shared__ unsigned char smem[];
    const uint32_t sb = smem_u32(smem);
    const int tid = threadIdx.x;
    const int wid = tid >> 5, lane = tid & 31;
    const int cta_m = blockIdx.x >> 4;
    const int cta_n = blockIdx.x & 15;
    const int m0 = cta_m * 32, n0 = cta_n * 32;
    unsigned int* bar_out = (cta_n < 8) ? &g_barA[cta_m * 32] : &g_barB[cta_m * 32];
    unsigned int* barA = &g_barA[cta_m * 32];
    unsigned int* barB = &g_barB[cta_m * 32];

    // W tile (resident)
    for (int idx = tid; idx < 32 * 512; idx += 160) {
        int r = idx / 512, k = idx & 511;
        float w = W_hh[(size_t)(n0 + r) * Hn + k];
        __nv_bfloat16 hi = __float2bfloat16(w);
        __nv_bfloat16 lo = __float2bfloat16(w - __bfloat162float(hi));
        *(__nv_bfloat16*)(smem + OFF_WHI + r * ROWB + k * 2) = hi;
        *(__nv_bfloat16*)(smem + OFF_WLO + r * ROWB + k * 2) = lo;
    }
    if (tid == 0) {
        MBI(sb + OFF_BAR + 0, 1);  MBI(sb + OFF_BAR + 8, 1);
        MBI(sb + OFF_BAR + 16, 1); MBI(sb + OFF_BAR + 24, 1);
    }
    __syncthreads();

    // MMA-warp lane constants
    const int wm = wid & 1, wn = wid >> 1;
    const int gq = lane >> 2, tq = lane & 3;
    const int ja = lane >> 3, ra = lane & 7;
    const int r0 = m0 + wm * 16 + gq;
    const int r1 = r0 + 8;
    const int r_loc = wm * 16 + (ja & 1) * 8 + ra;
    const uint32_t a_rowbase = (uint32_t)r_loc * 512;
    const uint32_t rl = (uint32_t)(r_loc & 7);
    const uint32_t uo = (uint32_t)(ja >> 1);
    const uint32_t b_off = (uint32_t)(wn * 16 + (ja >> 1) * 8 + ra) * ROWB + (uint32_t)(ja & 1) * 16;
    const int col0 = n0 + wn * 16 + tq * 2;
    const int rle0 = wm * 16 + gq;
    unsigned char* const img_hi_base = (unsigned char*)g_ihi4;
    unsigned char* const img_lo_base = (unsigned char*)g_ilo4;
    const size_t grp_off = (size_t)cta_m * 32768;

    for (int t = 0; t < Tn; t++) {
        const int rb = t & 1, wb = rb ^ 1;

        if (wid == 4) {
            if (lane == 0) {
                const unsigned char* shi = (const unsigned char*)g_ihi4[rb] + grp_off;
                const unsigned char* slo = (const unsigned char*)g_ilo4[rb] + grp_off;
                unsigned int target = (unsigned int)t * 8u;
                if (t > 0) {
                    bar_arrive(bar_out);             // completion of step t-1
                    while (bar_ld(barA) < target) { }
                }
                MBTX(sb + OFF_BAR + 0, 16384u);
                bulk_g2s(sb + OFF_AHI, shi, 16384u, sb + OFF_BAR + 0);
                MBTX(sb + OFF_BAR + 8, 16384u);
                bulk_g2s(sb + OFF_ALO, slo, 16384u, sb + OFF_BAR + 8);
                if (t > 0) { while (bar_ld(barB) < target) { } }
                MBTX(sb + OFF_BAR + 16, 16384u);
                bulk_g2s(sb + OFF_AHI + 16384, shi + 16384, 16384u, sb + OFF_BAR + 16);
                MBTX(sb + OFF_BAR + 24, 16384u);
                bulk_g2s(sb + OFF_ALO + 16384, slo + 16384, 16384u, sb + OFF_BAR + 24);
            }
        } else {
            const float* xs_t = g_xs + (size_t)t * (Bsz * Hn);
            float2 xv[2][2];
            #pragma unroll
            for (int nt = 0; nt < 2; nt++) {
                xv[nt][0] = *(const float2*)(xs_t + (size_t)r0 * Hn + col0 + nt * 8);
                xv[nt][1] = *(const float2*)(xs_t + (size_t)r1 * Hn + col0 + nt * 8);
            }

            float c[2][4];
            #pragma unroll
            for (int i = 0; i < 2; i++)
                #pragma unroll
                for (int j = 0; j < 4; j++) c[i][j] = 0.f;

            #pragma unroll
            for (int kc = 0; kc < 2; kc++) {
                // hi-pass: needs only A-hi (2 of 3 terms)
                MBW(sb + OFF_BAR + 16 * kc, t & 1);
                #pragma unroll 8
                for (int ks2 = 0; ks2 < 16; ks2++) {
                    uint32_t u = ((uint32_t)ks2 << 1) | uo;
                    uint32_t u2 = (u & 24u) | ((u & 7u) ^ rl);
                    uint32_t aoff = ((uint32_t)kc << 14) + a_rowbase + (u2 << 4);
                    uint32_t kb = (uint32_t)(kc * 16 + ks2) * 32;
                    uint32_t ahi[4], bhi[4], blo[4];
                    ldsm4(ahi, sb + OFF_AHI + aoff);
                    ldsm4(bhi, sb + OFF_WHI + b_off + kb);
                    ldsm4(blo, sb + OFF_WLO + b_off + kb);
                    mma_bf16(c[0], ahi, bhi[0], bhi[1]);
                    mma_bf16(c[0], ahi, blo[0], blo[1]);
                    mma_bf16(c[1], ahi, bhi[2], bhi[3]);
                    mma_bf16(c[1], ahi, blo[2], blo[3]);
                }
                // lo-pass: A-lo x W-hi
                MBW(sb + OFF_BAR + 16 * kc + 8, t & 1);
                #pragma unroll 8
                for (int ks2 = 0; ks2 < 16; ks2++) {
                    uint32_t u = ((uint32_t)ks2 << 1) | uo;
                    uint32_t u2 = (u & 24u) | ((u & 7u) ^ rl);
                    uint32_t aoff = ((uint32_t)kc << 14) + a_rowbase + (u2 << 4);
                    uint32_t kb = (uint32_t)(kc * 16 + ks2) * 32;
                    uint32_t alo[4], bhi[4];
                    ldsm4(alo, sb + OFF_ALO + aoff);
                    ldsm4(bhi, sb + OFF_WHI + b_off + kb);
                    mma_bf16(c[0], alo, bhi[0], bhi[1]);
                    mma_bf16(c[1], alo, bhi[2], bhi[3]);
                }
            }

            unsigned char* ohi = img_hi_base + (size_t)wb * 262144 + grp_off;
            unsigned char* olo = img_lo_base + (size_t)wb * 262144 + grp_off;
            #pragma unroll
            for (int nt = 0; nt < 2; nt++) {
                int col = col0 + nt * 8;
                int kc = col >> 8;
                uint32_t u = (uint32_t)((col & 255) >> 3);
                #pragma unroll
                for (int hf = 0; hf < 2; hf++) {
                    int rle = rle0 + hf * 8;
                    float s0 = ftanh(c[nt][hf * 2]     + xv[nt][hf].x);
                    float s1 = ftanh(c[nt][hf * 2 + 1] + xv[nt][hf].y);
                    __nv_bfloat16 h0 = __float2bfloat16(s0);
                    __nv_bfloat16 h1 = __float2bfloat16(s1);
                    uint32_t wh = (uint32_t)__bfloat16_as_ushort(h0) | ((uint32_t)__bfloat16_as_ushort(h1) << 16);
                    uint32_t wl = pack_bf16x2(s0 - __bfloat162float(h0), s1 - __bfloat162float(h1));
                    uint32_t u2 = (u & 24u) | ((u & 7u) ^ (uint32_t)(rle & 7));
                    uint32_t off = (uint32_t)kc * 16384u + (uint32_t)rle * 512u + (u2 << 4) + (uint32_t)(tq * 4);
                    *(uint32_t*)(ohi + off) = wh;
                    *(uint32_t*)(olo + off) = wl;
                    if (t == Tn - 1)
                        *(float2*)(g_hT + (size_t)(m0 + rle) * Hn + col) = make_float2(s0, s1);
                }
            }
        }
        __syncthreads();
    }
}

// ---------------- final FC ----------------
__global__ void fc_kernel(const float* __restrict__ fc_w, const float* __restrict__ fc_b,
                          float* __restrict__ out) {
    int b = blockIdx.x;
    float acc = 0.f;
    for (int k = threadIdx.x; k < Hn; k += 128)
        acc += g_hT[b * Hn + k] * fc_w[k];
    __shared__ float s[128];
    s[threadIdx.x] = acc;
    __syncthreads();
    #pragma unroll
    for (int o = 64; o > 0; o >>= 1) {
        if (threadIdx.x < o) s[threadIdx.x] += s[threadIdx.x + o];
        __syncthreads();
    }
    if (threadIdx.x == 0) out[b] = s[0] + fc_b[0];
}

extern "C" void kernel_launch(void* const* d_in, const int* in_sizes, int n_in,
                              void* d_out, int out_size) {
    const float* x    = (const float*)d_in[0];
    const float* W_ih = (const float*)d_in[1];
    const float* W_hh = (const float*)d_in[2];
    const float* b_ih = (const float*)d_in[3];
    const float* b_hh = (const float*)d_in[4];
    const float* fc_w = (const float*)d_in[5];
    const float* fc_b = (const float*)d_in[6];
    float* out = (float*)d_out;

    cudaFuncSetAttribute(xs_mma_kernel, cudaFuncAttributeMaxDynamicSharedMemorySize, SMEM_X2);
    cudaFuncSetAttribute(rnn_persist, cudaFuncAttributeMaxDynamicSharedMemorySize, SMEM_RP);

    init_kernel<<<256, 256>>>();
    dim3 gx(Hn / 64, (Tn * Bsz) / 64);   // (8, 1024)
    xs_mma_kernel<<<gx, 256, SMEM_X2>>>(x, W_ih, b_ih, b_hh);
    rnn_persist<<<NCTA, 160, SMEM_RP>>>(W_hh);
    fc_kernel<<<Bsz, 128>>>(fc_w, fc_b, out);
}